// round 12
// baseline (speedup 1.0000x reference)
#include <cuda_runtime.h>
#include <math.h>

// A[b,i,j] = softmax_i(s_i + s_j + bias) = exp(s_i)/sum_i' exp(s_i')
// (s_j and bias cancel under softmax over axis=1). Output row (b,i,:) is a
// constant p[b,i] broadcast N wide.
//
// Plain 3-kernel pipeline (R10/R11 lesson: PDL secondaries squat on SMs and
// regress; plain launches win for a ~1.5us primary):
//  K1: dot+exp (4 rows/warp, MLP=8) + per-block partial sums
//  K2: tiny (B blocks): fixed-order inv reduce + g_v = g_e * inv
//  K3: HEADLESS fill (scalar ldg, no smem, no sync, 16 regs) — the only
//      shape measured at ~7 TB/s effective store bandwidth.

#define MAX_BN   16384    // B*N for B=4, N=4096
#define K1_THREADS 256    // 8 warps * 4 rows = 32 rows/block
#define ROWS_PER_WARP 4
#define MAX_PART  1024

__device__ float g_e[MAX_BN];        // exp(s)
__device__ float g_v[MAX_BN];        // e * inv  (fill reads only this)
__device__ float g_part[MAX_PART];   // per-block partial sums

// ---- K1: dot + exp + block partial sum ----
__global__ void __launch_bounds__(K1_THREADS)
dot_exp_kernel(const float* __restrict__ h,
               const float* __restrict__ w,
               int BN, int D4) {
    __shared__ float s_warp[K1_THREADS / 32];

    const int warp = threadIdx.x >> 5;
    const int lane = threadIdx.x & 31;
    const int row0 = blockIdx.x * (K1_THREADS / 32 * ROWS_PER_WARP) + warp * ROWS_PER_WARP;

    const float4* wv = reinterpret_cast<const float4*>(w);
    float e_sum = 0.0f;

    if (D4 == 64 && row0 + ROWS_PER_WARP <= BN) {
        float4 b0 = __ldg(wv + lane);
        float4 b1 = __ldg(wv + lane + 32);
        float4 a0[ROWS_PER_WARP], a1[ROWS_PER_WARP];
        #pragma unroll
        for (int r = 0; r < ROWS_PER_WARP; r++) {
            const float4* hr = reinterpret_cast<const float4*>(h) + (size_t)(row0 + r) * 64;
            a0[r] = __ldg(hr + lane);
            a1[r] = __ldg(hr + lane + 32);
        }
        #pragma unroll
        for (int r = 0; r < ROWS_PER_WARP; r++) {
            float acc = a0[r].x * b0.x + a0[r].y * b0.y + a0[r].z * b0.z + a0[r].w * b0.w
                      + a1[r].x * b1.x + a1[r].y * b1.y + a1[r].z * b1.z + a1[r].w * b1.w;
            #pragma unroll
            for (int o = 16; o; o >>= 1)
                acc += __shfl_xor_sync(0xFFFFFFFFu, acc, o);
            float ev = __expf(acc);
            if (lane == 0) {
                g_e[row0 + r] = ev;
                e_sum += ev;                 // sequential in r: deterministic
            }
        }
    } else {
        for (int r = 0; r < ROWS_PER_WARP; r++) {
            int row = row0 + r;
            if (row >= BN) break;
            const float4* hr = reinterpret_cast<const float4*>(h) + (size_t)row * D4;
            float acc = 0.0f;
            for (int c = lane; c < D4; c += 32) {
                float4 a = __ldg(hr + c);
                float4 b = __ldg(wv + c);
                acc += a.x * b.x + a.y * b.y + a.z * b.z + a.w * b.w;
            }
            #pragma unroll
            for (int o = 16; o; o >>= 1)
                acc += __shfl_xor_sync(0xFFFFFFFFu, acc, o);
            if (lane == 0) {
                float ev = __expf(acc);
                g_e[row] = ev;
                e_sum += ev;
            }
        }
    }

    if (lane == 0) s_warp[warp] = e_sum;
    __syncthreads();
    if (threadIdx.x == 0) {
        float p = 0.0f;
        #pragma unroll
        for (int i = 0; i < K1_THREADS / 32; i++) p += s_warp[i];  // fixed order
        g_part[blockIdx.x] = p;
    }
}

// ---- K2: one block per batch -> inv (fixed order), then v = e*inv ----
__global__ void __launch_bounds__(256)
prep_kernel(int N, int parts_per_batch) {
    __shared__ float inv_s;
    const int tid = threadIdx.x;
    const int b   = blockIdx.x;

    if (tid < 32) {
        // fixed-order vectorized reduce of this batch's partials
        const float4* p4 = reinterpret_cast<const float4*>(g_part)
                         + ((size_t)b * parts_per_batch >> 2);
        int nvec = parts_per_batch >> 2;
        float p = 0.0f;
        for (int k = tid; k < nvec; k += 32) {
            float4 q = __ldg(p4 + k);
            p += (q.x + q.y) + (q.z + q.w);
        }
        #pragma unroll
        for (int o = 16; o; o >>= 1)
            p += __shfl_xor_sync(0xFFFFFFFFu, p, o);
        if (tid == 0) inv_s = 1.0f / p;
    }
    __syncthreads();
    float inv = inv_s;

    const size_t base = (size_t)b * N;
    for (int i = tid; i < N; i += 256)
        g_v[base + i] = g_e[base + i] * inv;
}

// ---- K3: HEADLESS fill — proven ~7TB/s shape ----
__global__ void __launch_bounds__(256)
fill_kernel(float4* __restrict__ out, int N4) {
    size_t row = blockIdx.x;
    float v = __ldg(&g_v[row]);
    float4 v4 = make_float4(v, v, v, v);
    float4* o = out + row * (size_t)N4;
    #pragma unroll 4
    for (int c = threadIdx.x; c < N4; c += blockDim.x)
        __stcs(&o[c], v4);
}

extern "C" void kernel_launch(void* const* d_in, const int* in_sizes, int n_in,
                              void* d_out, int out_size) {
    const float* h = (const float*)d_in[0];
    const float* w = (const float*)d_in[1];
    // d_in[2] (bias) cancels in the softmax over axis=1 -> unused.

    int D  = in_sizes[1];                       // 256
    int BN = in_sizes[0] / D;                   // B*N = 16384
    int N  = (int)((long long)out_size / BN);   // 4096
    int B  = BN / N;                            // 4

    int rows_per_block = (K1_THREADS / 32) * ROWS_PER_WARP;     // 32
    int k1_blocks = (BN + rows_per_block - 1) / rows_per_block; // 512
    dot_exp_kernel<<<k1_blocks, K1_THREADS>>>(h, w, BN, D >> 2);

    int parts_per_batch = k1_blocks / B;                        // 128
    prep_kernel<<<B, 256>>>(N, parts_per_batch);

    fill_kernel<<<BN, 256>>>((float4*)d_out, N >> 2);
}

// round 13
// speedup vs baseline: 1.1235x; 1.1235x over previous
#include <cuda_runtime.h>
#include <math.h>

// A[b,i,j] = softmax_i(s_i + s_j + bias) = exp(s_i)/sum_i' exp(s_i')
// (s_j and bias cancel under softmax over axis=1). Output row (b,i,:) is a
// constant p[b,i] broadcast N wide.
//
// Champion structure (R8, 43.5us): TWO launches only.
//  K1: dot+exp (4 rows/warp, MLP=8) + per-block partial sums (no atomics)
//  K2: fill — 8 rows/block, 512 thr, interleaved 8-stream store loop.
//      Head: per-batch inv reduce, vectorized (1 LDG.128/lane), fixed order.
// 12-round lesson: every extra launch costs ~2-3us; 2 launches is optimal.

#define MAX_BN   16384    // B*N for B=4, N=4096
#define K1_THREADS 256    // 8 warps * 4 rows = 32 rows/block
#define ROWS_PER_WARP 4
#define MAX_PART  1024
#define FILL_ROWS 8       // rows per fill block
#define FILL_THREADS 512

__device__ float g_e[MAX_BN];        // exp(s)
__device__ float g_part[MAX_PART];   // per-block partial sums

// ---- K1: dot + exp + block partial sum ----
__global__ void __launch_bounds__(K1_THREADS)
dot_exp_kernel(const float* __restrict__ h,
               const float* __restrict__ w,
               int BN, int D4) {
    __shared__ float s_warp[K1_THREADS / 32];

    const int warp = threadIdx.x >> 5;
    const int lane = threadIdx.x & 31;
    const int row0 = blockIdx.x * (K1_THREADS / 32 * ROWS_PER_WARP) + warp * ROWS_PER_WARP;

    const float4* wv = reinterpret_cast<const float4*>(w);
    float e_sum = 0.0f;

    if (D4 == 64 && row0 + ROWS_PER_WARP <= BN) {
        float4 b0 = __ldg(wv + lane);
        float4 b1 = __ldg(wv + lane + 32);
        // batch all 8 h loads up front (MLP=8)
        float4 a0[ROWS_PER_WARP], a1[ROWS_PER_WARP];
        #pragma unroll
        for (int r = 0; r < ROWS_PER_WARP; r++) {
            const float4* hr = reinterpret_cast<const float4*>(h) + (size_t)(row0 + r) * 64;
            a0[r] = __ldg(hr + lane);
            a1[r] = __ldg(hr + lane + 32);
        }
        #pragma unroll
        for (int r = 0; r < ROWS_PER_WARP; r++) {
            float acc = a0[r].x * b0.x + a0[r].y * b0.y + a0[r].z * b0.z + a0[r].w * b0.w
                      + a1[r].x * b1.x + a1[r].y * b1.y + a1[r].z * b1.z + a1[r].w * b1.w;
            #pragma unroll
            for (int o = 16; o; o >>= 1)
                acc += __shfl_xor_sync(0xFFFFFFFFu, acc, o);
            float ev = __expf(acc);
            if (lane == 0) {
                g_e[row0 + r] = ev;
                e_sum += ev;                 // sequential in r: deterministic
            }
        }
    } else {
        for (int r = 0; r < ROWS_PER_WARP; r++) {
            int row = row0 + r;
            if (row >= BN) break;
            const float4* hr = reinterpret_cast<const float4*>(h) + (size_t)row * D4;
            float acc = 0.0f;
            for (int c = lane; c < D4; c += 32) {
                float4 a = __ldg(hr + c);
                float4 b = __ldg(wv + c);
                acc += a.x * b.x + a.y * b.y + a.z * b.z + a.w * b.w;
            }
            #pragma unroll
            for (int o = 16; o; o >>= 1)
                acc += __shfl_xor_sync(0xFFFFFFFFu, acc, o);
            if (lane == 0) {
                float ev = __expf(acc);
                g_e[row] = ev;
                e_sum += ev;
            }
        }
    }

    if (lane == 0) s_warp[warp] = e_sum;
    __syncthreads();
    if (threadIdx.x == 0) {
        float p = 0.0f;
        #pragma unroll
        for (int i = 0; i < K1_THREADS / 32; i++) p += s_warp[i];  // fixed order
        g_part[blockIdx.x] = p;
    }
}

// ---- K2: vectorized inv head (amortized over 8 rows) + interleaved fill ----
__global__ void __launch_bounds__(FILL_THREADS)
fill_kernel(const float* __restrict__ e,
            float4* __restrict__ out,
            int N4, int parts_per_batch) {
    __shared__ float inv_s;
    __shared__ float v_s[FILL_ROWS];

    const int tid = threadIdx.x;

    // warp 0: one LDG.128 per lane, fixed order -> deterministic, 1 L2 trip
    if (tid < 32) {
        const float4* p4 = reinterpret_cast<const float4*>(g_part)
                         + ((size_t)blockIdx.y * parts_per_batch >> 2);
        int nvec = parts_per_batch >> 2;              // 32 for 128 partials
        float p = 0.0f;
        for (int k = tid; k < nvec; k += 32) {
            float4 q = __ldg(p4 + k);
            p += (q.x + q.y) + (q.z + q.w);
        }
        #pragma unroll
        for (int o = 16; o; o >>= 1)
            p += __shfl_xor_sync(0xFFFFFFFFu, p, o);
        if (tid == 0) inv_s = 1.0f / p;
    }
    __syncthreads();

    size_t row0 = (size_t)blockIdx.y * ((size_t)gridDim.x * FILL_ROWS)
                + (size_t)blockIdx.x * FILL_ROWS;
    if (tid < FILL_ROWS)
        v_s[tid] = __ldg(&e[row0 + tid]) * inv_s;
    __syncthreads();

    // interleaved 8-stream store loop (champion shape)
    float4* o = out + row0 * (size_t)N4;
    #pragma unroll
    for (int c = tid; c < N4; c += FILL_THREADS) {
        #pragma unroll
        for (int r = 0; r < FILL_ROWS; r++) {
            float v = v_s[r];
            __stcs(o + (size_t)r * N4 + c, make_float4(v, v, v, v));
        }
    }
}

extern "C" void kernel_launch(void* const* d_in, const int* in_sizes, int n_in,
                              void* d_out, int out_size) {
    const float* h = (const float*)d_in[0];
    const float* w = (const float*)d_in[1];
    // d_in[2] (bias) cancels in the softmax over axis=1 -> unused.

    int D  = in_sizes[1];                       // 256
    int BN = in_sizes[0] / D;                   // B*N = 16384
    int N  = (int)((long long)out_size / BN);   // 4096
    int B  = BN / N;                            // 4

    float* e = nullptr;
    cudaGetSymbolAddress((void**)&e, g_e);

    int rows_per_block = (K1_THREADS / 32) * ROWS_PER_WARP;     // 32
    int k1_blocks = (BN + rows_per_block - 1) / rows_per_block; // 512
    dot_exp_kernel<<<k1_blocks, K1_THREADS>>>(h, w, BN, D >> 2);

    int parts_per_batch = k1_blocks / B;                        // 128
    dim3 grid(N / FILL_ROWS, B);                                // 512 x 4
    fill_kernel<<<grid, FILL_THREADS>>>(e, (float4*)d_out, N >> 2, parts_per_batch);
}